// round 4
// baseline (speedup 1.0000x reference)
#include <cuda_runtime.h>

// FuzzyARTMAP single fused kernel: match scores + row sums + argmax.
// N=1024, D=256, C=512, fp32. match[n,c] = sum_d min(x,w) / sum_d x; gate 0.75;
// first-occurrence argmax. Argmax finalized in-kernel via threadfence reduction
// across the 8 column-blocks of each row; state arrays self-reset each launch.

#define N_ROWS 1024
#define D_DIM  256
#define C_CATS 512
#define VIG    0.75f

#define BM 64
#define BN 64
#define BK 64
#define NCB (C_CATS / BN)     // column-blocks per row = 8
#define LSTRIDE 68            // 16B-aligned rows; 16-row stride pattern covers banks 2x (optimal)

__device__ unsigned long long g_key[N_ROWS];   // zero at load; reset by finisher each launch
__device__ unsigned int       g_cnt[N_ROWS];   // zero at load; reset by finisher each launch

// ---------------------------------------------------------------------------
__global__ __launch_bounds__(512) void fused_kernel(const float* __restrict__ x,
                                                    const float* __restrict__ w,
                                                    float* __restrict__ out,
                                                    float* __restrict__ idx_out) {
    __shared__ float As[BM][LSTRIDE];             // x tile [m][k]
    __shared__ float Bs[BN][LSTRIDE];             // w tile [c][k]
    __shared__ float xq[BM][8];                   // per-row 1/8 sums of x
    __shared__ unsigned long long skey[BM];       // per-row best (val, col) key

    const int t  = threadIdx.x;
    const int tx = t & 15;        // 16 thread-columns
    const int ty = t >> 4;        // 32 thread-rows
    const int rowBase = blockIdx.y * BM;
    const int colBase = blockIdx.x * BN;

    float acc[2][4];
    #pragma unroll
    for (int i = 0; i < 2; i++)
        #pragma unroll
        for (int j = 0; j < 4; j++) acc[i][j] = 0.f;

    float xpart = 0.f;
    const int xr = t >> 3;        // xsum duty: 8 threads per row
    const int xc = (t & 7) * 8;

    if (t < BM) skey[t] = 0ull;

    for (int k0 = 0; k0 < D_DIM; k0 += BK) {
        // Load 64x64 tiles: 1024 float4 per tile, 2 per thread per tile.
        #pragma unroll
        for (int i = 0; i < 2; i++) {
            int idx = t + 512 * i;
            int r   = idx >> 4;
            int c4  = idx & 15;
            *(float4*)&As[r][4 * c4] =
                *(const float4*)(x + (size_t)(rowBase + r) * D_DIM + k0 + 4 * c4);
            *(float4*)&Bs[r][4 * c4] =
                *(const float4*)(w + (size_t)(colBase + r) * D_DIM + k0 + 4 * c4);
        }
        __syncthreads();

        // Fused row-sum: each thread sums an 8-wide slice of one As row.
        {
            float4 v0 = *(const float4*)&As[xr][xc];
            float4 v1 = *(const float4*)&As[xr][xc + 4];
            xpart += (v0.x + v0.y) + (v0.z + v0.w) + (v1.x + v1.y) + (v1.z + v1.w);
        }

        #pragma unroll 4
        for (int k = 0; k < BK; k += 4) {
            float4 a0 = *(const float4*)&As[2 * ty + 0][k];
            float4 a1 = *(const float4*)&As[2 * ty + 1][k];
            float4 b0 = *(const float4*)&Bs[tx +  0][k];
            float4 b1 = *(const float4*)&Bs[tx + 16][k];
            float4 b2 = *(const float4*)&Bs[tx + 32][k];
            float4 b3 = *(const float4*)&Bs[tx + 48][k];

            #define STEP(F)                                \
                acc[0][0] += fminf(a0.F, b0.F);           \
                acc[0][1] += fminf(a0.F, b1.F);           \
                acc[0][2] += fminf(a0.F, b2.F);           \
                acc[0][3] += fminf(a0.F, b3.F);           \
                acc[1][0] += fminf(a1.F, b0.F);           \
                acc[1][1] += fminf(a1.F, b1.F);           \
                acc[1][2] += fminf(a1.F, b2.F);           \
                acc[1][3] += fminf(a1.F, b3.F);
            STEP(x) STEP(y) STEP(z) STEP(w)
            #undef STEP
        }
        __syncthreads();
    }

    xq[xr][t & 7] = xpart;
    __syncthreads();

    // Epilogue: divide, gate, store, per-row argmax key.
    #pragma unroll
    for (int i = 0; i < 2; i++) {
        int r = 2 * ty + i;
        int n = rowBase + r;
        float xs = ((xq[r][0] + xq[r][1]) + (xq[r][2] + xq[r][3]))
                 + ((xq[r][4] + xq[r][5]) + (xq[r][6] + xq[r][7]));
        unsigned long long bk = 0ull;
        #pragma unroll
        for (int j = 0; j < 4; j++) {
            int c = colBase + tx + 16 * j;
            float m = acc[i][j] / xs;                  // exact division, as reference
            float g = (m >= VIG) ? m : 0.f;
            out[(size_t)n * C_CATS + c] = g;
            // order-preserving key: larger value wins; ties -> smaller column
            unsigned long long key =
                ((unsigned long long)__float_as_uint(g) << 32) |
                (unsigned long long)(unsigned)(C_CATS - 1 - c);
            if (key > bk) bk = key;
        }
        atomicMax(&skey[r], bk);
    }
    __syncthreads();

    // Cross-block argmax finalization (threadfence reduction over 8 col-blocks).
    if (t < BM) {
        int n = rowBase + t;
        atomicMax(&g_key[n], skey[t]);
        __threadfence();
        unsigned old = atomicAdd(&g_cnt[n], 1u);
        if (old == NCB - 1) {                          // last column-block for this row
            __threadfence();
            unsigned long long k = atomicMax(&g_key[n], 0ull);   // atomic read
            if (idx_out)
                idx_out[n] = (float)(C_CATS - 1 - (unsigned)(k & 0xffffffffull));
            g_key[n] = 0ull;                           // self-clean for next replay
            g_cnt[n] = 0u;
        }
    }
}

// ---------------------------------------------------------------------------
extern "C" void kernel_launch(void* const* d_in, const int* in_sizes, int n_in,
                              void* d_out, int out_size) {
    const float* x = (const float*)d_in[0];
    const float* w = (const float*)d_in[1];
    float* out = (float*)d_out;

    float* idx_out = (out_size >= N_ROWS * C_CATS + N_ROWS)
                   ? out + (size_t)N_ROWS * C_CATS : nullptr;

    dim3 grid(C_CATS / BN, N_ROWS / BM);   // (8, 16) = 128 blocks
    fused_kernel<<<grid, 512>>>(x, w, out, idx_out);
}